// round 1
// baseline (speedup 1.0000x reference)
#include <cuda_runtime.h>
#include <cuda_fp16.h>
#include <cstdint>

// Problem constants
#define OUT_N   8192
#define IN_K    8192
#define BATCH   64
#define GROUP   128
#define CHUNKS  (IN_K / GROUP)   // 64 K-chunks, one scale per (row, chunk)
#define TILE_N  64               // output rows per CTA
#define NTHREADS 256             // 8 warps
#define AS_STRIDE 136            // 128 + 8 halfs padding (bank-conflict-free ldmatrix)

// Static scratch: x converted to fp16 (1 MiB). Allowed (no runtime alloc).
__device__ __half g_xh[BATCH * IN_K];

// ---------------------------------------------------------------------------
// Kernel 1: convert x (fp32) -> fp16 scratch
// ---------------------------------------------------------------------------
__global__ __launch_bounds__(256) void convert_x_kernel(const float* __restrict__ x) {
    int i = blockIdx.x * 256 + threadIdx.x;          // one float4 per thread
    float4 v = reinterpret_cast<const float4*>(x)[i];
    __half2 h01 = __floats2half2_rn(v.x, v.y);
    __half2 h23 = __floats2half2_rn(v.z, v.w);
    uint2 o;
    o.x = *reinterpret_cast<uint32_t*>(&h01);
    o.y = *reinterpret_cast<uint32_t*>(&h23);
    reinterpret_cast<uint2*>(g_xh)[i] = o;
}

// ---------------------------------------------------------------------------
// ldmatrix / mma wrappers
// ---------------------------------------------------------------------------
__device__ __forceinline__ void ldsm_x4(uint32_t& r0, uint32_t& r1, uint32_t& r2,
                                        uint32_t& r3, uint32_t addr) {
    asm volatile("ldmatrix.sync.aligned.m8n8.x4.shared.b16 {%0,%1,%2,%3}, [%4];"
                 : "=r"(r0), "=r"(r1), "=r"(r2), "=r"(r3) : "r"(addr));
}
__device__ __forceinline__ void ldsm_x2(uint32_t& r0, uint32_t& r1, uint32_t addr) {
    asm volatile("ldmatrix.sync.aligned.m8n8.x2.shared.b16 {%0,%1}, [%2];"
                 : "=r"(r0), "=r"(r1) : "r"(addr));
}
__device__ __forceinline__ void mma_16816(float* c, uint32_t a0, uint32_t a1,
                                          uint32_t a2, uint32_t a3,
                                          uint32_t b0, uint32_t b1) {
    asm volatile(
        "mma.sync.aligned.m16n8k16.row.col.f32.f16.f16.f32 "
        "{%0,%1,%2,%3},{%4,%5,%6,%7},{%8,%9},{%0,%1,%2,%3};"
        : "+f"(c[0]), "+f"(c[1]), "+f"(c[2]), "+f"(c[3])
        : "r"(a0), "r"(a1), "r"(a2), "r"(a3), "r"(b0), "r"(b1));
}

// ---------------------------------------------------------------------------
// Kernel 2: int4-dequant GEMM.  Grid = 128 CTAs (OUT/TILE_N), 256 threads.
// Each warp owns 8 output columns (n), all 64 batch rows (4 m16 tiles).
// ---------------------------------------------------------------------------
__global__ __launch_bounds__(NTHREADS) void dequant_gemm_kernel(
    const int*   __restrict__ packed,   // [OUT_N, IN_K/2] int32 (one byte each)
    const float* __restrict__ scales,   // [OUT_N, CHUNKS]
    float*       __restrict__ out)      // [BATCH, OUT_N]
{
    __shared__ __align__(16) __half As[BATCH][AS_STRIDE];   // x chunk  (64 x 128)
    __shared__ __align__(16) __half Bs[TILE_N][AS_STRIDE];  // dequant W chunk
    __shared__ float sS[TILE_N];

    const int tid  = threadIdx.x;
    const int warp = tid >> 5;
    const int lane = tid & 31;
    const int n0   = blockIdx.x * TILE_N;

    float acc[4][4];
    #pragma unroll
    for (int m = 0; m < 4; m++)
        #pragma unroll
        for (int j = 0; j < 4; j++) acc[m][j] = 0.f;

    const uint4* pk4 = reinterpret_cast<const uint4*>(packed); // row stride 1024 uint4

    uint4 aV[4], pV[4];
    float sreg = 0.f;

    // -- register prefetch of one chunk's global data ------------------------
    auto load_chunk = [&](int ch) {
        #pragma unroll
        for (int i = 0; i < 4; i++) {
            int v    = tid + i * NTHREADS;     // 0..1023
            int row  = v >> 4;                 // 0..63
            int kv   = v & 15;                 // 16B unit within 128-k chunk
            aV[i] = *reinterpret_cast<const uint4*>(
                        &g_xh[row * IN_K + ch * GROUP + kv * 8]);
            pV[i] = pk4[(size_t)(n0 + row) * (IN_K / 8) + ch * 16 + kv];
        }
        if (tid < TILE_N) sreg = scales[(size_t)(n0 + tid) * CHUNKS + ch];
    };

    load_chunk(0);

    const uint32_t as_base = (uint32_t)__cvta_generic_to_shared(&As[0][0]);
    const uint32_t bs_base = (uint32_t)__cvta_generic_to_shared(&Bs[0][0]);
    const uint32_t c1032b  = 0x64086408u;      // half2(1032,1032): exact
    const __half2  c1032   = *reinterpret_cast<const __half2*>(&c1032b);

    for (int ch = 0; ch < CHUNKS; ch++) {
        __syncthreads();   // previous MMA phase done reading As/Bs

        // stage A + scales
        #pragma unroll
        for (int i = 0; i < 4; i++) {
            int v = tid + i * NTHREADS;
            int row = v >> 4, kv = v & 15;
            *reinterpret_cast<uint4*>(&As[row][kv * 8]) = aV[i];
        }
        if (tid < TILE_N) sS[tid] = sreg;
        __syncthreads();   // sS visible

        // dequant: 8 weights (4 bytes payload) -> 4 fp16x2 -> one STS.128
        #pragma unroll
        for (int i = 0; i < 4; i++) {
            int v = tid + i * NTHREADS;
            int row = v >> 4, kv = v & 15;
            __half2 s2 = __float2half2_rn(sS[row]);
            uint32_t w[4] = { pV[i].x, pV[i].y, pV[i].z, pV[i].w };
            uint4 outv;
            uint32_t* r = reinterpret_cast<uint32_t*>(&outv);
            #pragma unroll
            for (int j = 0; j < 4; j++) {
                // byte -> (1024+q_lo, 1024+q_hi) fp16x2, exact
                uint32_t t = ((w[j] * 0x1001u) & 0x000F000Fu) | 0x64006400u;
                __half2 hv = *reinterpret_cast<__half2*>(&t);
                hv = __hmul2(__hsub2(hv, c1032), s2);   // (q-8)*s, one rounding
                r[j] = *reinterpret_cast<uint32_t*>(&hv);
            }
            *reinterpret_cast<uint4*>(&Bs[row][kv * 8]) = outv;
        }
        __syncthreads();   // Bs ready

        // prefetch next chunk (LDGs overlap the MMA phase below)
        if (ch + 1 < CHUNKS) load_chunk(ch + 1);

        // -- MMA phase: 8 k16 tiles x 4 m16 tiles, warp's n8 slice ----------
        #pragma unroll
        for (int kt = 0; kt < 8; kt++) {
            uint32_t b0, b1;
            {
                int br = warp * 8 + (lane & 7);
                int bc = kt * 16 + ((lane >> 3) & 1) * 8;
                ldsm_x2(b0, b1, bs_base + (uint32_t)(br * AS_STRIDE + bc) * 2);
            }
            #pragma unroll
            for (int mt = 0; mt < 4; mt++) {
                uint32_t a0, a1, a2, a3;
                int ar = mt * 16 + (lane & 15);
                int ac = kt * 16 + (lane >> 4) * 8;
                ldsm_x4(a0, a1, a2, a3,
                        as_base + (uint32_t)(ar * AS_STRIDE + ac) * 2);
                mma_16816(acc[mt], a0, a1, a2, a3, b0, b1);
            }
        }
    }

    // epilogue: C frag rows = batch, cols = output channel
    #pragma unroll
    for (int mt = 0; mt < 4; mt++) {
        int m = mt * 16 + (lane >> 2);
        int n = n0 + warp * 8 + (lane & 3) * 2;
        float2 v01 = make_float2(acc[mt][0], acc[mt][1]);
        float2 v23 = make_float2(acc[mt][2], acc[mt][3]);
        *reinterpret_cast<float2*>(&out[(size_t)m * OUT_N + n])       = v01;
        *reinterpret_cast<float2*>(&out[(size_t)(m + 8) * OUT_N + n]) = v23;
    }
}

// ---------------------------------------------------------------------------
extern "C" void kernel_launch(void* const* d_in, const int* in_sizes, int n_in,
                              void* d_out, int out_size) {
    const float* x      = (const float*)d_in[0];
    const int*   packed = (const int*)d_in[1];
    const float* scales = (const float*)d_in[2];
    float*       out    = (float*)d_out;

    // 524288 floats / 4 per thread = 131072 threads
    convert_x_kernel<<<512, 256>>>(x);
    dequant_gemm_kernel<<<OUT_N / TILE_N, NTHREADS>>>(packed, scales, out);
}

// round 6
// speedup vs baseline: 1.3202x; 1.3202x over previous
#include <cuda_runtime.h>
#include <cuda_fp16.h>
#include <cstdint>

// ---------------------------------------------------------------------------
// Problem constants
// ---------------------------------------------------------------------------
#define OUT_N    8192
#define IN_K     8192
#define BATCH    64
#define GROUP    128                  // k per chunk (= scale group)
#define TILE_N   128                  // W rows per CTA
#define KSPLIT   4
#define NGRPS    (OUT_N / TILE_N)     // 64
#define CHPC     (64 / KSPLIT)        // 16 chunks per CTA
#define NTHREADS 256

// SMEM layout (bytes). Padded row stride: 136 halfs = 272 B (conflict-free ldmatrix)
#define RSTRIDE     272
#define W_BYTES     (TILE_N * RSTRIDE)     // 34816
#define X_OFF       W_BYTES
#define X_BYTES     (BATCH * RSTRIDE)      // 17408
#define STAGE_BYTES (W_BYTES + X_BYTES)    // 52224
#define SCALE_OFF   (2 * STAGE_BYTES)      // 104448
#define SCALE_BYTES (CHPC * TILE_N * 4)    // 8192
#define SMEM_TOTAL  (SCALE_OFF + SCALE_BYTES)  // 112640  (2 CTAs/SM fit in 228KB)

// Static scratch: x converted to fp16 (1 MiB)
__device__ __half g_xh[BATCH * IN_K];

// ---------------------------------------------------------------------------
// PTX helpers (family-portable only: no tcgen05 — ptxas targets sm_103)
// ---------------------------------------------------------------------------
__device__ __forceinline__ void ldsm_x4(uint32_t& r0, uint32_t& r1, uint32_t& r2,
                                        uint32_t& r3, uint32_t addr) {
    asm volatile("ldmatrix.sync.aligned.m8n8.x4.shared.b16 {%0,%1,%2,%3}, [%4];"
                 : "=r"(r0), "=r"(r1), "=r"(r2), "=r"(r3) : "r"(addr));
}
__device__ __forceinline__ void ldsm_x2(uint32_t& r0, uint32_t& r1, uint32_t addr) {
    asm volatile("ldmatrix.sync.aligned.m8n8.x2.shared.b16 {%0,%1}, [%2];"
                 : "=r"(r0), "=r"(r1) : "r"(addr));
}
__device__ __forceinline__ void mma_16816(float* c, uint32_t a0, uint32_t a1,
                                          uint32_t a2, uint32_t a3,
                                          uint32_t b0, uint32_t b1) {
    asm volatile(
        "mma.sync.aligned.m16n8k16.row.col.f32.f16.f16.f32 "
        "{%0,%1,%2,%3},{%4,%5,%6,%7},{%8,%9},{%0,%1,%2,%3};"
        : "+f"(c[0]), "+f"(c[1]), "+f"(c[2]), "+f"(c[3])
        : "r"(a0), "r"(a1), "r"(a2), "r"(a3), "r"(b0), "r"(b1));
}
__device__ __forceinline__ void cp_async16(uint32_t dst, const void* src) {
    asm volatile("cp.async.cg.shared.global [%0], [%1], 16;"
                 :: "r"(dst), "l"(src) : "memory");
}
__device__ __forceinline__ void cp_commit() {
    asm volatile("cp.async.commit_group;" ::: "memory");
}

// ---------------------------------------------------------------------------
// Kernel 1: convert x fp32->fp16 AND zero-init out (both 131072 float4 units)
// ---------------------------------------------------------------------------
__global__ __launch_bounds__(256) void prep_kernel(const float* __restrict__ x,
                                                   float* __restrict__ out) {
    int i = blockIdx.x * 256 + threadIdx.x;
    float4 v = reinterpret_cast<const float4*>(x)[i];
    __half2 h01 = __floats2half2_rn(v.x, v.y);
    __half2 h23 = __floats2half2_rn(v.z, v.w);
    uint2 o;
    o.x = *reinterpret_cast<uint32_t*>(&h01);
    o.y = *reinterpret_cast<uint32_t*>(&h23);
    reinterpret_cast<uint2*>(g_xh)[i] = o;
    reinterpret_cast<float4*>(out)[i] = make_float4(0.f, 0.f, 0.f, 0.f);
}

// ---------------------------------------------------------------------------
// Kernel 2: int4-dequant GEMM (mma.sync), double-buffered, k-split atomics.
// Grid = 256 CTAs: bid & 63 = n-group (128 W rows), bid >> 6 = k-group.
// Warp w owns output cols n0 + w*16 .. +15 (2 n8 frags), all 64 batch rows.
// ---------------------------------------------------------------------------
__global__ __launch_bounds__(NTHREADS, 2)
void dq_gemm_kernel(const int*   __restrict__ packed,
                    const float* __restrict__ scales,
                    float*       __restrict__ out)
{
    extern __shared__ __align__(16) char dsm[];
    const uint32_t sb = (uint32_t)__cvta_generic_to_shared(dsm);
    float* sScale = reinterpret_cast<float*>(dsm + SCALE_OFF);

    const int tid  = threadIdx.x;
    const int wid  = tid >> 5;
    const int lane = tid & 31;
    const int n0   = (blockIdx.x & 63) * TILE_N;
    const int kc0  = (blockIdx.x >> 6) * CHPC;

    float acc[4][2][4];
    #pragma unroll
    for (int m = 0; m < 4; m++)
        #pragma unroll
        for (int n = 0; n < 2; n++)
            #pragma unroll
            for (int j = 0; j < 4; j++) acc[m][n][j] = 0.f;

    const uint4* pk4 = reinterpret_cast<const uint4*>(packed); // row stride 1024 uint4
    const uint32_t c1032b = 0x64086408u;                       // half2(1032,1032)
    const __half2 c1032 = *reinterpret_cast<const __half2*>(&c1032b);

    // ---- stage the scale table once: [CHPC][TILE_N] -----------------------
    #pragma unroll
    for (int i = 0; i < (CHPC * TILE_N) / NTHREADS; i++) {
        int idx = tid + i * NTHREADS;                // 0..2047
        int ch = idx >> 7, row = idx & 127;
        sScale[idx] = scales[(size_t)(n0 + row) * 64 + kc0 + ch];
    }

    // ---- packed-W register prefetch (one chunk = 2048 uint4 = 8/thread) ---
    uint4 pv[8];
    auto prefetch = [&](int kc) {
        #pragma unroll
        for (int i = 0; i < 8; i++) {
            int u = tid + (i << 8);                  // 0..2047
            int row = u >> 4, kv = u & 15;
            pv[i] = pk4[(size_t)(n0 + row) * 1024 + kc * 16 + kv];
        }
    };

    // ---- x tile cp.async (1024 x 16B units = 4/thread) --------------------
    auto stage_x = [&](int kc, int s) {
        const uint32_t xb = sb + s * STAGE_BYTES + X_OFF;
        #pragma unroll
        for (int j = 0; j < 4; j++) {
            int u = tid + (j << 8);                  // 0..1023
            int b = u >> 4, kv = u & 15;
            cp_async16(xb + b * RSTRIDE + kv * 16,
                       &g_xh[(size_t)b * IN_K + kc * GROUP + kv * 8]);
        }
        cp_commit();
    };

    prefetch(kc0);
    stage_x(kc0, 0);

    for (int ch = 0; ch < CHPC; ch++) {
        const int s = ch & 1;
        const uint32_t stage = sb + s * STAGE_BYTES;

        __syncthreads();                  // MMA(ch-1) done; scale table ready

        if (ch + 1 < CHPC) stage_x(kc0 + ch + 1, s ^ 1);

        // dequant pv -> W stage (8 x STS.128 per thread)
        #pragma unroll
        for (int i = 0; i < 8; i++) {
            int u = tid + (i << 8);
            int row = u >> 4, kv = u & 15;
            __half2 s2 = __float2half2_rn(sScale[(ch << 7) + row]);
            uint32_t w[4] = { pv[i].x, pv[i].y, pv[i].z, pv[i].w };
            uint32_t o[4];
            #pragma unroll
            for (int j = 0; j < 4; j++) {
                uint32_t t = ((w[j] * 0x1001u) & 0x000F000Fu) | 0x64006400u;
                __half2 hv = __hmul2(__hsub2(*reinterpret_cast<__half2*>(&t), c1032), s2);
                o[j] = *reinterpret_cast<uint32_t*>(&hv);
            }
            asm volatile("st.shared.v4.b32 [%0], {%1,%2,%3,%4};"
                         :: "r"(stage + row * RSTRIDE + kv * 16),
                            "r"(o[0]), "r"(o[1]), "r"(o[2]), "r"(o[3]) : "memory");
        }

        if (ch + 1 < CHPC) prefetch(kc0 + ch + 1);   // LDGs overlap MMA below

        if (ch + 1 < CHPC)
            asm volatile("cp.async.wait_group 1;" ::: "memory");
        else
            asm volatile("cp.async.wait_group 0;" ::: "memory");
        __syncthreads();                  // W[s], x[s] visible

        // ---- MMA phase: warp's 2 n8 frags x 4 m16 tiles x 8 k16 tiles -----
        const uint32_t wbase = stage;
        const uint32_t xbase = stage + X_OFF;
        #pragma unroll
        for (int kt = 0; kt < 8; kt++) {
            uint32_t b0[2], b1[2];
            #pragma unroll
            for (int nt = 0; nt < 2; nt++) {
                int br = wid * 16 + nt * 8 + (lane & 7);
                int bc = kt * 16 + ((lane >> 3) & 1) * 8;
                ldsm_x2(b0[nt], b1[nt], wbase + (uint32_t)(br * RSTRIDE + bc * 2));
            }
            #pragma unroll
            for (int mt = 0; mt < 4; mt++) {
                uint32_t a0, a1, a2, a3;
                int ar = mt * 16 + (lane & 15);
                int ac = kt * 16 + (lane >> 4) * 8;
                ldsm_x4(a0, a1, a2, a3, xbase + (uint32_t)(ar * RSTRIDE + ac * 2));
                mma_16816(acc[mt][0], a0, a1, a2, a3, b0[0], b1[0]);
                mma_16816(acc[mt][1], a0, a1, a2, a3, b0[1], b1[1]);
            }
        }
    }

    // ---- epilogue: vectorized float2 atomics (k-split merge) --------------
    #pragma unroll
    for (int mt = 0; mt < 4; mt++) {
        #pragma unroll
        for (int nt = 0; nt < 2; nt++) {
            int m = mt * 16 + (lane >> 2);
            int n = n0 + wid * 16 + nt * 8 + (lane & 3) * 2;
            atomicAdd(reinterpret_cast<float2*>(&out[(size_t)m * OUT_N + n]),
                      make_float2(acc[mt][nt][0], acc[mt][nt][1]));
            atomicAdd(reinterpret_cast<float2*>(&out[(size_t)(m + 8) * OUT_N + n]),
                      make_float2(acc[mt][nt][2], acc[mt][nt][3]));
        }
    }
}

// ---------------------------------------------------------------------------
extern "C" void kernel_launch(void* const* d_in, const int* in_sizes, int n_in,
                              void* d_out, int out_size) {
    const float* x      = (const float*)d_in[0];
    const int*   packed = (const int*)d_in[1];
    const float* scales = (const float*)d_in[2];
    float*       out    = (float*)d_out;

    cudaFuncSetAttribute(dq_gemm_kernel,
                         cudaFuncAttributeMaxDynamicSharedMemorySize, SMEM_TOTAL);

    prep_kernel<<<512, 256>>>(x, out);
    dq_gemm_kernel<<<NGRPS * KSPLIT, NTHREADS, SMEM_TOTAL>>>(packed, scales, out);
}

// round 7
// speedup vs baseline: 1.3589x; 1.0294x over previous
#include <cuda_runtime.h>
#include <cuda_fp16.h>
#include <cstdint>

// ---------------------------------------------------------------------------
// Problem constants
// ---------------------------------------------------------------------------
#define OUT_N    8192
#define IN_K     8192
#define BATCH    64
#define GROUP    128                  // k per chunk (= scale group)
#define TILE_N   128                  // W rows per CTA
#define KSPLIT   8
#define NGRPS    (OUT_N / TILE_N)     // 64
#define CHPC     (64 / KSPLIT)        // 8 chunks per CTA
#define NTHREADS 256

// SMEM layout (bytes). Padded row stride: 136 halfs = 272 B (16B-mult, odd x16)
#define RSTRIDE     272
#define W_BYTES     (TILE_N * RSTRIDE)     // 34816
#define X_OFF       W_BYTES
#define X_BYTES     (BATCH * RSTRIDE)      // 17408
#define STAGE_BYTES (W_BYTES + X_BYTES)    // 52224
#define SCALE_OFF   (2 * STAGE_BYTES)      // 104448
#define SCALE_BYTES (CHPC * TILE_N * 4)    // 4096
#define SMEM_TOTAL  (SCALE_OFF + SCALE_BYTES)  // 108544 -> 2 CTAs/SM

// Static scratch: x converted to fp16 (1 MiB)
__device__ __half g_xh[BATCH * IN_K];

// ---------------------------------------------------------------------------
// PTX helpers (family-portable: ptxas target is sm_103, no tcgen05)
// ---------------------------------------------------------------------------
__device__ __forceinline__ void ldsm_x4(uint32_t& r0, uint32_t& r1, uint32_t& r2,
                                        uint32_t& r3, uint32_t addr) {
    asm volatile("ldmatrix.sync.aligned.m8n8.x4.shared.b16 {%0,%1,%2,%3}, [%4];"
                 : "=r"(r0), "=r"(r1), "=r"(r2), "=r"(r3) : "r"(addr));
}
__device__ __forceinline__ void mma_16816(float* c, uint32_t a0, uint32_t a1,
                                          uint32_t a2, uint32_t a3,
                                          uint32_t b0, uint32_t b1) {
    asm volatile(
        "mma.sync.aligned.m16n8k16.row.col.f32.f16.f16.f32 "
        "{%0,%1,%2,%3},{%4,%5,%6,%7},{%8,%9},{%0,%1,%2,%3};"
        : "+f"(c[0]), "+f"(c[1]), "+f"(c[2]), "+f"(c[3])
        : "r"(a0), "r"(a1), "r"(a2), "r"(a3), "r"(b0), "r"(b1));
}
__device__ __forceinline__ void cp_async16(uint32_t dst, const void* src) {
    asm volatile("cp.async.cg.shared.global [%0], [%1], 16;"
                 :: "r"(dst), "l"(src) : "memory");
}
__device__ __forceinline__ void cp_commit() {
    asm volatile("cp.async.commit_group;" ::: "memory");
}

// ---------------------------------------------------------------------------
// Kernel 1: convert x fp32->fp16 AND zero-init out (both 131072 float4 units)
// ---------------------------------------------------------------------------
__global__ __launch_bounds__(256) void prep_kernel(const float* __restrict__ x,
                                                   float* __restrict__ out) {
    int i = blockIdx.x * 256 + threadIdx.x;
    float4 v = reinterpret_cast<const float4*>(x)[i];
    __half2 h01 = __floats2half2_rn(v.x, v.y);
    __half2 h23 = __floats2half2_rn(v.z, v.w);
    uint2 o;
    o.x = *reinterpret_cast<uint32_t*>(&h01);
    o.y = *reinterpret_cast<uint32_t*>(&h23);
    reinterpret_cast<uint2*>(g_xh)[i] = o;
    reinterpret_cast<float4*>(out)[i] = make_float4(0.f, 0.f, 0.f, 0.f);
}

// ---------------------------------------------------------------------------
// Kernel 2: int4-dequant GEMM (mma.sync), double-buffered, k-split atomics.
// Grid = 512 CTAs: bid & 63 = n-group (128 W rows), bid >> 6 = k-group (8 ch).
// Warp layout 2(m) x 4(n): warp owns 32 batch rows x 32 output cols.
//   m-half  = wid & 1   -> rows  (wid&1)*32 + mt*16,  mt = 0..1
//   n-group = wid >> 1  -> cols  (wid>>1)*32 + nt*8,  nt = 0..3
// ---------------------------------------------------------------------------
__global__ __launch_bounds__(NTHREADS, 2)
void dq_gemm_kernel(const int*   __restrict__ packed,
                    const float* __restrict__ scales,
                    float*       __restrict__ out)
{
    extern __shared__ __align__(16) char dsm[];
    const uint32_t sb = (uint32_t)__cvta_generic_to_shared(dsm);
    float* sScale = reinterpret_cast<float*>(dsm + SCALE_OFF);

    const int tid  = threadIdx.x;
    const int wid  = tid >> 5;
    const int lane = tid & 31;
    const int mh   = wid & 1;          // batch half
    const int ng   = wid >> 1;         // 32-col group
    const int n0   = (blockIdx.x & 63) * TILE_N;
    const int kc0  = (blockIdx.x >> 6) * CHPC;

    float acc[2][4][4];
    #pragma unroll
    for (int m = 0; m < 2; m++)
        #pragma unroll
        for (int n = 0; n < 4; n++)
            #pragma unroll
            for (int j = 0; j < 4; j++) acc[m][n][j] = 0.f;

    const uint4* pk4 = reinterpret_cast<const uint4*>(packed); // row stride 1024
    const uint32_t c1032b = 0x64086408u;                       // half2(1032,1032)
    const __half2 c1032 = *reinterpret_cast<const __half2*>(&c1032b);

    // ---- stage the scale table once: [CHPC][TILE_N] -----------------------
    #pragma unroll
    for (int i = 0; i < (CHPC * TILE_N) / NTHREADS; i++) {
        int idx = tid + i * NTHREADS;                // 0..1023
        int ch = idx >> 7, row = idx & 127;
        sScale[idx] = scales[(size_t)(n0 + row) * 64 + kc0 + ch];
    }

    // ---- packed-W register prefetch (one chunk = 2048 uint4 = 8/thread) ---
    uint4 pv[8];
    auto prefetch = [&](int kc) {
        #pragma unroll
        for (int i = 0; i < 8; i++) {
            int u = tid + (i << 8);                  // 0..2047
            int row = u >> 4, kv = u & 15;
            pv[i] = pk4[(size_t)(n0 + row) * 1024 + kc * 16 + kv];
        }
    };

    // ---- x tile cp.async (1024 x 16B units = 4/thread) --------------------
    auto stage_x = [&](int kc, int s) {
        const uint32_t xb = sb + s * STAGE_BYTES + X_OFF;
        #pragma unroll
        for (int j = 0; j < 4; j++) {
            int u = tid + (j << 8);                  // 0..1023
            int b = u >> 4, kv = u & 15;
            cp_async16(xb + b * RSTRIDE + kv * 16,
                       &g_xh[(size_t)b * IN_K + kc * GROUP + kv * 8]);
        }
        cp_commit();
    };

    prefetch(kc0);
    stage_x(kc0, 0);

    for (int ch = 0; ch < CHPC; ch++) {
        const int s = ch & 1;
        const uint32_t stage = sb + s * STAGE_BYTES;

        __syncthreads();                  // MMA(ch-1) done; scale table ready

        if (ch + 1 < CHPC) stage_x(kc0 + ch + 1, s ^ 1);

        // dequant pv -> W stage (8 x STS.128 per thread)
        #pragma unroll
        for (int i = 0; i < 8; i++) {
            int u = tid + (i << 8);
            int row = u >> 4, kv = u & 15;
            __half2 s2 = __float2half2_rn(sScale[(ch << 7) + row]);
            uint32_t w[4] = { pv[i].x, pv[i].y, pv[i].z, pv[i].w };
            uint32_t o[4];
            #pragma unroll
            for (int j = 0; j < 4; j++) {
                uint32_t t = ((w[j] * 0x1001u) & 0x000F000Fu) | 0x64006400u;
                __half2 hv = __hmul2(__hsub2(*reinterpret_cast<__half2*>(&t), c1032), s2);
                o[j] = *reinterpret_cast<uint32_t*>(&hv);
            }
            asm volatile("st.shared.v4.b32 [%0], {%1,%2,%3,%4};"
                         :: "r"(stage + row * RSTRIDE + kv * 16),
                            "r"(o[0]), "r"(o[1]), "r"(o[2]), "r"(o[3]) : "memory");
        }

        if (ch + 1 < CHPC) prefetch(kc0 + ch + 1);   // LDGs overlap MMA below

        if (ch + 1 < CHPC)
            asm volatile("cp.async.wait_group 1;" ::: "memory");
        else
            asm volatile("cp.async.wait_group 0;" ::: "memory");
        __syncthreads();                  // W[s], x[s] visible

        // ---- MMA phase: 8 k16 tiles, warp tile 32(m) x 32(n) --------------
        const uint32_t wbase = stage;
        const uint32_t xbase = stage + X_OFF;
        #pragma unroll
        for (int kt = 0; kt < 8; kt++) {
            // B: two ldsm_x4, each covers 2 n8 frags x both k-halves
            uint32_t b[4][2];             // [nt][b0,b1]
            #pragma unroll
            for (int np = 0; np < 2; np++) {
                int br = ng * 32 + np * 16 + ((lane >> 4) & 1) * 8 + (lane & 7);
                int bc = kt * 16 + ((lane >> 3) & 1) * 8;
                ldsm_x4(b[np*2][0], b[np*2][1], b[np*2+1][0], b[np*2+1][1],
                        wbase + (uint32_t)(br * RSTRIDE + bc * 2));
            }
            // A: two ldsm_x4 (mt = 0,1), rows mh*32 + mt*16
            #pragma unroll
            for (int mt = 0; mt < 2; mt++) {
                uint32_t a0, a1, a2, a3;
                int ar = mh * 32 + mt * 16 + (lane & 15);
                int ac = kt * 16 + (lane >> 4) * 8;
                ldsm_x4(a0, a1, a2, a3, xbase + (uint32_t)(ar * RSTRIDE + ac * 2));
                #pragma unroll
                for (int nt = 0; nt < 4; nt++)
                    mma_16816(acc[mt][nt], a0, a1, a2, a3, b[nt][0], b[nt][1]);
            }
        }
    }

    // ---- epilogue: vectorized float2 atomics (k-split merge) --------------
    #pragma unroll
    for (int mt = 0; mt < 2; mt++) {
        #pragma unroll
        for (int nt = 0; nt < 4; nt++) {
            int m = mh * 32 + mt * 16 + (lane >> 2);
            int n = n0 + ng * 32 + nt * 8 + (lane & 3) * 2;
            atomicAdd(reinterpret_cast<float2*>(&out[(size_t)m * OUT_N + n]),
                      make_float2(acc[mt][nt][0], acc[mt][nt][1]));
            atomicAdd(reinterpret_cast<float2*>(&out[(size_t)(m + 8) * OUT_N + n]),
                      make_float2(acc[mt][nt][2], acc[mt][nt][3]));
        }
    }
}

// ---------------------------------------------------------------------------
extern "C" void kernel_launch(void* const* d_in, const int* in_sizes, int n_in,
                              void* d_out, int out_size) {
    const float* x      = (const float*)d_in[0];
    const int*   packed = (const int*)d_in[1];
    const float* scales = (const float*)d_in[2];
    float*       out    = (float*)d_out;

    cudaFuncSetAttribute(dq_gemm_kernel,
                         cudaFuncAttributeMaxDynamicSharedMemorySize, SMEM_TOTAL);

    prep_kernel<<<512, 256>>>(x, out);
    dq_gemm_kernel<<<NGRPS * KSPLIT, NTHREADS, SMEM_TOTAL>>>(packed, scales, out);
}